// round 8
// baseline (speedup 1.0000x reference)
#include <cuda_runtime.h>
#include <cuda_bf16.h>
#include <math.h>

// Box-embedding conditional-probability loss. B pairs, D=128.
// R8 = R7 with the uint32_t compile fix (use unsigned int, no <cstdint>).
// Latency-bound kernel; ptxas won't hold register-resident load batches
// (R5/R6). Decouple MLP from the register file with cp.async (LDGSTS)
// double-buffered SMEM staging. Per-warp autonomous pipeline:
// 4 stages x 4 pairs x 2KB, prefetch stage i+1 while computing stage i.

#define EPS_F 1e-8f

#define WARPS_PER_BLOCK 4
#define G_PER_WARP      4          // stages (pair-groups) per warp
#define PAIRS_PER_GROUP 4
#define ROW_BYTES       512        // one table row: 128 fp32
#define STAGE_BYTES     (PAIRS_PER_GROUP * 4 * ROW_BYTES)   // 8192
#define WARP_SMEM       (2 * STAGE_BYTES)                   // double buffer
#define BLOCK_SMEM      (WARPS_PER_BLOCK * WARP_SMEM)       // 65536

static __device__ __forceinline__ void cp_async16(unsigned int dst, const void* src) {
    asm volatile("cp.async.cg.shared.global [%0], [%1], 16;\n"
                 :: "r"(dst), "l"(src));
}
static __device__ __forceinline__ void cp_commit() {
    asm volatile("cp.async.commit_group;\n" ::: "memory");
}
template <int N>
static __device__ __forceinline__ void cp_wait() {
    asm volatile("cp.async.wait_group %0;\n" :: "n"(N) : "memory");
}

static __device__ __forceinline__ float split_mant(float p, int& e) {
    int ib = __float_as_int(p);
    e += ((ib >> 23) & 0xFF) - 127;
    return __int_as_float((ib & 0x007FFFFF) | 0x3F800000);  // [1,2)
}

__global__ void __launch_bounds__(WARPS_PER_BLOCK * 32)
box_pair_kernel(const int* __restrict__ t1x,
                const int* __restrict__ t2x,
                const float* __restrict__ min_tab,
                const float* __restrict__ dlt_tab,
                float* __restrict__ out_pos,
                float* __restrict__ out_neg,
                int B)
{
    extern __shared__ char smem[];

    const float MIN_MEAN   = (float)((0.0001 + 0.01) / 2.0);
    const float MIN_VAR    = (float)(0.01 - (0.0001 + 0.01) / 2.0);
    const float DELTA_MEAN = (float)((0.9 + 0.999) / 2.0);
    const float DELTA_VAR  = (float)(0.999 - (0.9 + 0.999) / 2.0);
    const unsigned int FULL = 0xFFFFFFFFu;

    int warpid = threadIdx.x >> 5;
    int lane   = threadIdx.x & 31;
    int sub    = lane & 7;          // lane within 8-lane pair group
    int g      = lane >> 3;         // pair group 0..3 (compute phase)

    int wglob  = blockIdx.x * WARPS_PER_BLOCK + warpid;   // global warp id

    char* wsmem = smem + warpid * WARP_SMEM;
    unsigned int wsaddr = (unsigned int)__cvta_generic_to_shared(wsmem);

    // ---------- prefetch a stage: 16 rows of 512B via cp.async ----------
    auto prefetch = [&](int it, int buf) {
        int pb = (wglob * G_PER_WARP + it) * PAIRS_PER_GROUP;  // pair base
        if (pb >= B) { cp_commit(); return; }
        int pidx = pb + (lane & 3);
        if (pidx >= B) pidx = B - 1;
        int i1v = __ldg(t1x + pidx);
        int i2v = __ldg(t2x + pidx);
        unsigned int dst = wsaddr + buf * STAGE_BYTES + lane * 16;
#pragma unroll
        for (int r = 0; r < 16; r++) {
            int p = r >> 2;                               // pair in group
            int tok = __shfl_sync(FULL, (r & 2) ? i2v : i1v, p);
            const float* tab = (r & 1) ? dlt_tab : min_tab;
            cp_async16(dst + r * ROW_BYTES,
                       tab + (size_t)tok * 128 + lane * 4);
        }
        cp_commit();
    };

    prefetch(0, 0);

#pragma unroll
    for (int it = 0; it < G_PER_WARP; it++) {
        if (it + 1 < G_PER_WARP) {
            prefetch(it + 1, (it + 1) & 1);
            cp_wait<1>();          // stage `it` complete (it+1 still in flight)
        } else {
            cp_wait<0>();
        }
        __syncwarp();              // all lanes' copies visible to all lanes

        int pb   = (wglob * G_PER_WARP + it) * PAIRS_PER_GROUP;
        int pair = pb + g;
        bool live = (pair < B);

        // my pair's 4 rows: m1,d1,m2,d2 at +0,+512,+1024,+1536
        const char* pbase = wsmem + ((it & 1) * STAGE_BYTES) + g * 2048 + sub * 16;

        float p1 = 1.0f, p2 = 1.0f, pm = 1.0f, pj = 1.0f;
        float mr = 3.4e38f;

#pragma unroll
        for (int c = 0; c < 4; c++) {
            float4 m1 = *(const float4*)(pbase +    0 + c * 128);
            float4 d1 = *(const float4*)(pbase +  512 + c * 128);
            float4 m2 = *(const float4*)(pbase + 1024 + c * 128);
            float4 d2 = *(const float4*)(pbase + 1536 + c * 128);

            const float* m1v = &m1.x;
            const float* d1v = &d1.x;
            const float* m2v = &m2.x;
            const float* d2v = &d2.x;
#pragma unroll
            for (int j = 0; j < 4; j++) {
                float a  = fmaf(m1v[j], MIN_VAR, MIN_MEAN);
                float da = fmaf(d1v[j], DELTA_VAR, DELTA_MEAN);
                float c0 = fmaf(m2v[j], MIN_VAR, MIN_MEAN);
                float dc = fmaf(d2v[j], DELTA_VAR, DELTA_MEAN);
                float b  = a + da;
                float d  = c0 + dc;

                float jmin = fminf(a, c0);
                float jmax = fmaxf(b, d);
                float ej   = jmax - jmin;       // join extent
                float em   = (da + dc) - ej;    // meet extent (min+max=sum)

                mr = fminf(mr, em);
                p1 *= da;
                p2 *= dc;
                pj *= ej;
                pm *= em;   // clamp dropped: em<=0 only in disjoint branch,
                            // where pm is discarded
            }
        }

        int EM = 0;
        pm = split_mant(pm, EM);   // keep cross-lane meet product fp32-safe

        float rm = __fdividef(pm, p2);   // -> meet_log - t2_log
        float rj = __fdividef(pj, p1);   // -> join_log - t1_log

#pragma unroll
        for (int off = 4; off > 0; off >>= 1) {
            rm *= __shfl_xor_sync(FULL, rm, off);
            rj *= __shfl_xor_sync(FULL, rj, off);
            EM += __shfl_xor_sync(FULL, EM, off);
        }

        unsigned int ball = __ballot_sync(FULL, mr <= 0.0f);
        bool disjoint = ((ball >> (lane & 24)) & 0xFFu) != 0u;

        if (sub == 0 && live) {
            const float LN2 = 0.69314718055994530942f;
            float posv, negv;
            if (disjoint) {
                posv = logf(rj);
                negv = 0.0f;
            } else {
                float cond = logf(rm) + (float)EM * LN2;  // log P(t1|t2)
                posv = -cond;
                negv = -logf(fmaxf(1.0f - expf(cond), EPS_F));
            }
            out_pos[pair] = posv;
            out_neg[pair] = negv;
        }
        __syncwarp();   // reads done before next prefetch overwrites buffer
    }
}

extern "C" void kernel_launch(void* const* d_in, const int* in_sizes, int n_in,
                              void* d_out, int out_size) {
    const int*   t1x    = (const int*)d_in[0];
    const int*   t2x    = (const int*)d_in[1];
    const float* min_tb = (const float*)d_in[2];
    const float* dlt_tb = (const float*)d_in[3];

    int B = in_sizes[0];
    float* out_pos = (float*)d_out;
    float* out_neg = (float*)d_out + B;

    static int configured = 0;
    if (!configured) {
        cudaFuncSetAttribute(box_pair_kernel,
                             cudaFuncAttributeMaxDynamicSharedMemorySize,
                             BLOCK_SMEM);
        cudaFuncSetAttribute(box_pair_kernel,
                             cudaFuncAttributePreferredSharedMemoryCarveout,
                             100);
        configured = 1;
    }

    int pairs_per_block = WARPS_PER_BLOCK * G_PER_WARP * PAIRS_PER_GROUP; // 64
    int grid = (B + pairs_per_block - 1) / pairs_per_block;
    box_pair_kernel<<<grid, WARPS_PER_BLOCK * 32, BLOCK_SMEM>>>(
        t1x, t2x, min_tb, dlt_tb, out_pos, out_neg, B);
}